// round 13
// baseline (speedup 1.0000x reference)
#include <cuda_runtime.h>
#include <cuda_fp16.h>

#define B_   4
#define C_   19
#define HI   64
#define WI   128
#define HO   512
#define WO   1024
#define NPIX   (B_*HO*WO)
#define NBLK   (4*512*4)
#define NSLOT  64
#define SLOTSZ 32768
#define NCOL   40
#define LOG2E  1.4426950408889634f
#define LN2f   0.6931471805599453f
#define LP2T  (-0.5145731728f)   /* log2(0.7) */

typedef unsigned long long ull;

// ---------------- device scratch (zero at module load; last block re-zeroes) ----
__device__ float    g_oh[2][2][64];        // [loss][{cnt,sum}][slot]
__device__ float    g_bce4[B_][4][32];     // [sample][{S1,S0,pos,neg}][slot]
__device__ int      g_ms[2][NSLOT][8];     // counter at [l][slot][0], 32B padded
__device__ unsigned g_done;
__device__ uint2    g_comp[2][NPIX];       // 64 regions of 32768 per loss

__device__ __forceinline__ float ex2(float x) {
    float y; asm("ex2.approx.f32 %0, %1;" : "=f"(y) : "f"(x)); return y;
}
__device__ __forceinline__ float lg2(float x) {
    float y; asm("lg2.approx.f32 %0, %1;" : "=f"(y) : "f"(x)); return y;
}
__device__ __forceinline__ unsigned h2bits(float lo, float hi) {
    __half2 h = __floats2half2_rn(lo, hi);
    return *reinterpret_cast<unsigned*>(&h);
}

struct SA { uint2 prh[C_][NCOL]; float sred[8][8]; };
struct SB { unsigned hist[2048]; float redS[8], redC[8];
            double shb[4]; float shoh[2][4]; float s_ex[2][2]; float s_cle[2]; };

// ---------------- single fused kernel, register-capped ----------------
__global__ __launch_bounds__(256, 6) void fused_kernel(
    const float* __restrict__ mainp,
    const float* __restrict__ coarsep,
    const int*   __restrict__ seg,
    const float* __restrict__ bp,
    const float* __restrict__ bgt,
    float* __restrict__ out,
    int K)
{
    __shared__ union USm { SA a; SB b; __device__ USm() {} } sm;
    __shared__ unsigned s_pref;
    __shared__ int      s_r;
    __shared__ bool     amLast;

    const float SY = 63.f / 511.f;
    const float SX = 127.f / 1023.f;

    const int tid  = threadIdx.x;
    const int lane = tid & 31;
    const int warp = tid >> 5;
    const int oy = blockIdx.y;
    const int b  = blockIdx.z;
    const int xs = blockIdx.x * 256;
    const int blk  = blockIdx.x + 4 * (blockIdx.y + 512 * blockIdx.z);
    const int slot = blk & (NSLOT - 1);

    float fy  = oy * SY;
    int   y0  = (int)fy;
    int   y1  = min(y0 + 1, HI - 1);
    float wy  = fy - (float)y0;
    float w1y = 1.f - wy;

    int xbase4 = ((int)((float)xs * SX)) & ~3;   // 4-aligned; i0 in [0,35]

    const float* p0 = mainp   + (size_t)b * C_ * HI * WI;
    const float* p1 = coarsep + (size_t)b * C_ * HI * WI;

    // ---- stage 1: single pass, 171 tasks = (class, 4-col chunk), LDG.128 ----
    if (tid < C_ * 9) {
        int c = tid / 9;
        int k = tid - c * 9;
        int col0 = xbase4 + 4 * k;
        int ce   = min(col0 + 4, WI - 1);

        const float* rm0 = p0 + c * HI * WI + y0 * WI;
        const float* rm1 = p0 + c * HI * WI + y1 * WI;
        const float* rc0 = p1 + c * HI * WI + y0 * WI;
        const float* rc1 = p1 + c * HI * WI + y1 * WI;

        float4 m0 = *(const float4*)(rm0 + col0);
        float4 m1 = *(const float4*)(rm1 + col0);
        float4 q0 = *(const float4*)(rc0 + col0);
        float4 q1 = *(const float4*)(rc1 + col0);
        float em0 = rm0[ce], em1 = rm1[ce];
        float ec0 = rc0[ce], ec1 = rc1[ce];

        float vm0 = (m0.x * w1y + m1.x * wy) * LOG2E;
        float vm1 = (m0.y * w1y + m1.y * wy) * LOG2E;
        float vm2 = (m0.z * w1y + m1.z * wy) * LOG2E;
        float vm3 = (m0.w * w1y + m1.w * wy) * LOG2E;
        float vm4 = (em0  * w1y + em1  * wy) * LOG2E;
        float vc0 = (q0.x * w1y + q1.x * wy) * LOG2E;
        float vc1 = (q0.y * w1y + q1.y * wy) * LOG2E;
        float vc2 = (q0.z * w1y + q1.z * wy) * LOG2E;
        float vc3 = (q0.w * w1y + q1.w * wy) * LOG2E;
        float vc4 = (ec0  * w1y + ec1  * wy) * LOG2E;

        sm.a.prh[c][4*k + 0] = make_uint2(h2bits(vm0, vc0), h2bits(vm1 - vm0, vc1 - vc0));
        sm.a.prh[c][4*k + 1] = make_uint2(h2bits(vm1, vc1), h2bits(vm2 - vm1, vc2 - vc1));
        sm.a.prh[c][4*k + 2] = make_uint2(h2bits(vm2, vc2), h2bits(vm3 - vm2, vc3 - vc2));
        sm.a.prh[c][4*k + 3] = make_uint2(h2bits(vm3, vc3), h2bits(vm4 - vm3, vc4 - vc3));
    }
    __syncthreads();

    int   ox = xs + tid;
    float fx = (float)ox * SX;
    int   x0 = (int)fx;
    float wx = fx - (float)x0;
    int   i0 = x0 - xbase4;

    int  pix   = (b * HO + oy) * WO + ox;
    int  t     = seg[pix];
    bool valid = (t != 255);
    int  tc    = valid ? t : 0;
    if (tc >= C_) tc = C_ - 1;

    const uint2* prq = &sm.a.prh[0][0];
    __half2 wxh = __float2half2_rn(wx);

    __half2 acc0 = __float2half2_rn(0.f);
    __half2 acc1 = __float2half2_rn(0.f);
    #pragma unroll
    for (int c = 0; c < C_; c++) {
        uint2 q = prq[c * NCOL + i0];
        __half2 v = *reinterpret_cast<__half2*>(&q.x);
        __half2 d = *reinterpret_cast<__half2*>(&q.y);
        __half2 e = h2exp2(__hfma2(wxh, d, v));
        if (c & 1) acc1 = __hadd2(acc1, e);
        else       acc0 = __hadd2(acc0, e);
    }
    __half2 acc = __hadd2(acc0, acc1);
    float s_main = __low2float(acc);
    float s_coar = __high2float(acc);

    float vtm, vtc;
    {
        uint2 q = prq[tc * NCOL + i0];
        __half2 v = *reinterpret_cast<__half2*>(&q.x);
        __half2 d = *reinterpret_cast<__half2*>(&q.y);
        __half2 vt2 = __hfma2(wxh, d, v);
        vtm = __low2float(vt2);
        vtc = __high2float(vt2);
    }

    float lp2m = vtm - lg2(s_main);
    float lp2c = vtc - lg2(s_coar);

    float c0f = 0.f, c1f = 0.f, r1 = 0.f, r3 = 0.f;
    #pragma unroll
    for (int l = 0; l < 2; l++) {
        float lp2 = l ? lp2c : lp2m;
        bool le = valid && (lp2 <= LP2T);
        unsigned ble = __ballot_sync(0xffffffffu, le);
        if (l == 0) { c0f = (float)__popc(ble); if (le) r1 = -lp2 * LN2f; }
        else        { c1f = (float)__popc(ble); if (le) r3 = -lp2 * LN2f; }

        unsigned ball = ~ble;
        if (ball) {
            int ldr = __ffs(ball) - 1;
            int base = 0;
            if (lane == ldr) base = atomicAdd(&g_ms[l][slot][0], __popc(ball));
            base = __shfl_sync(0xffffffffu, base, ldr);
            if (!le) {
                float prob = valid ? ex2(lp2) : 1.0f;
                float nll  = -lp2 * LN2f;
                int rank = __popc(ball & ((1u << lane) - 1u));
                g_comp[l][slot * SLOTSZ + base + rank] =
                    make_uint2(__float_as_uint(prob),
                               __float_as_uint(valid ? nll : -1e30f));
            }
        }
    }

    // ---- boundary BCE ----
    float tb = bgt[pix];
    const float* pb = bp + (size_t)b * HI * WI;
    int x1 = min(x0 + 1, WI - 1);
    float v00 = pb[y0 * WI + x0], v01 = pb[y0 * WI + x1];
    float v10 = pb[y1 * WI + x0], v11 = pb[y1 * WI + x1];
    float top = v00 * (1.f - wx) + v01 * wx;
    float bot = v10 * (1.f - wx) + v11 * wx;
    float p   = top * w1y + bot * wy;

    bool  isP = (tb == 1.0f), isN = (tb == 0.0f);
    float r4 = isP ? fminf(fmaxf(-lg2(p)       * LN2f, 0.f), 100.f) : 0.f;
    float r5 = isN ? fminf(fmaxf(-lg2(1.f - p) * LN2f, 0.f), 100.f) : 0.f;
    float cp = (float)__popc(__ballot_sync(~0u, isP));
    float cn = (float)__popc(__ballot_sync(~0u, isN));

    // ---- block reduce ----
    #pragma unroll
    for (int o = 16; o > 0; o >>= 1) {
        r1 += __shfl_down_sync(~0u, r1, o);
        r3 += __shfl_down_sync(~0u, r3, o);
        r4 += __shfl_down_sync(~0u, r4, o);
        r5 += __shfl_down_sync(~0u, r5, o);
    }
    if (lane == 0) {
        sm.a.sred[warp][0] = c0f; sm.a.sred[warp][1] = r1;
        sm.a.sred[warp][2] = c1f; sm.a.sred[warp][3] = r3;
        sm.a.sred[warp][4] = r4;  sm.a.sred[warp][5] = r5;
        sm.a.sred[warp][6] = cp;  sm.a.sred[warp][7] = cn;
    }
    __syncthreads();
    if (tid < 8) {
        float acc2 = 0.f;
        #pragma unroll
        for (int w = 0; w < 8; w++) acc2 += sm.a.sred[w][tid];
        if (tid < 4) atomicAdd(&g_oh[tid >> 1][tid & 1][slot], acc2);
        else         atomicAdd(&g_bce4[b][tid - 4][blk & 31], acc2);
    }

    // ---- last-block detection ----
    __threadfence();
    __syncthreads();                            // ends smem-A usage
    if (tid == 0) amLast = (atomicAdd(&g_done, 1u) == (unsigned)(NBLK - 1));
    __syncthreads();
    if (!amLast) return;

    // =================== TAIL (one block, warm L2) ===================
    if (tid < 4) sm.b.s_ex[tid >> 1][tid & 1] = 0.f;
    if (tid < 128) {
        float v = __ldcg(&g_oh[tid >> 6][0][tid & 63]);
        #pragma unroll
        for (int o = 16; o > 0; o >>= 1) v += __shfl_down_sync(~0u, v, o);
        if (lane == 0) sm.b.redS[warp] = v;
    }
    __syncthreads();
    if (tid < 2) sm.b.s_cle[tid] = sm.b.redS[tid * 2] + sm.b.redS[tid * 2 + 1];
    __syncthreads();

    for (int l = 0; l < 2; l++) {
        int cLE = (int)(sm.b.s_cle[l] + 0.5f);
        if (cLE >= K) continue;                 // common path: thr = 0.7 exactly

        if (tid == 0) { s_r = K - 1 - cLE; s_pref = 0u; }
        __syncthreads();

        for (int lev = 0; lev < 3; lev++) {
            for (int i = tid; i < 2048; i += 256) sm.b.hist[i] = 0u;
            __syncthreads();
            unsigned pref = s_pref;
            for (int s = 0; s < NSLOT; s++) {
                int ms = __ldcg(&g_ms[l][s][0]);
                const uint2* sp = &g_comp[l][s * SLOTSZ];
                for (int i = tid; i < ms; i += 256) {
                    unsigned bits = __ldcg(&sp[i].x);
                    bool ok; unsigned bin;
                    if (lev == 0)      { ok = true;                 bin = bits >> 21; }
                    else if (lev == 1) { ok = (bits >> 21) == pref; bin = (bits >> 10) & 0x7FFu; }
                    else               { ok = (bits >> 10) == pref; bin = bits & 0x3FFu; }
                    if (ok) atomicAdd(&sm.b.hist[bin], 1u);
                }
            }
            __syncthreads();
            if (tid == 0) {
                int rr = s_r; unsigned cum = 0u;
                int nb = (lev == 2) ? 1024 : 2048;
                for (int i2 = 0; i2 < nb; i2++) {
                    unsigned h = sm.b.hist[i2];
                    if ((int)(cum + h) > rr) {
                        s_pref = (lev == 0) ? (unsigned)i2
                               : (lev == 1) ? ((pref << 11) | (unsigned)i2)
                                            : ((pref << 10) | (unsigned)i2);
                        s_r = rr - (int)cum;
                        break;
                    }
                    cum += h;
                }
            }
            __syncthreads();
        }
        unsigned thr_bits = s_pref;

        float es = 0.f, ec = 0.f;
        for (int s = 0; s < NSLOT; s++) {
            int ms = __ldcg(&g_ms[l][s][0]);
            const uint2* sp = &g_comp[l][s * SLOTSZ];
            for (int i = tid; i < ms; i += 256) {
                unsigned pbits = __ldcg(&sp[i].x);
                float nl = __uint_as_float(__ldcg(&sp[i].y));
                if (pbits <= thr_bits && nl > -1e29f) { es += nl; ec += 1.f; }
            }
        }
        #pragma unroll
        for (int o = 16; o > 0; o >>= 1) {
            es += __shfl_down_sync(~0u, es, o);
            ec += __shfl_down_sync(~0u, ec, o);
        }
        if (lane == 0) { sm.b.redS[warp] = es; sm.b.redC[warp] = ec; }
        __syncthreads();
        if (tid == 0) {
            float ts = 0.f, tc2 = 0.f;
            #pragma unroll
            for (int i = 0; i < 8; i++) { ts += sm.b.redS[i]; tc2 += sm.b.redC[i]; }
            sm.b.s_ex[l][0] = ts; sm.b.s_ex[l][1] = tc2;
        }
        __syncthreads();
    }

    // ---- finalize (first 128 threads) ----
    if (tid < 128) {
        float bs1  = __ldcg(&g_bce4[warp][0][lane]);
        float bs0  = __ldcg(&g_bce4[warp][1][lane]);
        float bpos = __ldcg(&g_bce4[warp][2][lane]);
        float bneg = __ldcg(&g_bce4[warp][3][lane]);
        float oc = 0.f, os = 0.f, oc1 = 0.f, os1 = 0.f;
        if (warp < 2) {
            oc  = __ldcg(&g_oh[0][0][tid]); os  = __ldcg(&g_oh[0][1][tid]);
            oc1 = __ldcg(&g_oh[1][0][tid]); os1 = __ldcg(&g_oh[1][1][tid]);
        }
        #pragma unroll
        for (int o = 16; o > 0; o >>= 1) {
            bs1 += __shfl_down_sync(~0u, bs1, o); bs0 += __shfl_down_sync(~0u, bs0, o);
            bpos += __shfl_down_sync(~0u, bpos, o); bneg += __shfl_down_sync(~0u, bneg, o);
            oc += __shfl_down_sync(~0u, oc, o); os += __shfl_down_sync(~0u, os, o);
            oc1 += __shfl_down_sync(~0u, oc1, o); os1 += __shfl_down_sync(~0u, os1, o);
        }
        if (lane == 0) {
            double denom = (double)bpos + (double)bneg;
            sm.b.shb[warp] = ((double)bneg * (double)bs1 + (double)bpos * (double)bs0) / denom;
            if (warp < 2) {
                sm.b.shoh[warp][0] = oc;  sm.b.shoh[warp][1] = os;
                sm.b.shoh[warp][2] = oc1; sm.b.shoh[warp][3] = os1;
            }
        }
    }
    __syncthreads();
    if (tid == 0) {
        double cnt0 = (double)sm.b.shoh[0][0] + (double)sm.b.shoh[1][0] + (double)sm.b.s_ex[0][1];
        double sum0 = (double)sm.b.shoh[0][1] + (double)sm.b.shoh[1][1] + (double)sm.b.s_ex[0][0];
        double cnt1 = (double)sm.b.shoh[0][2] + (double)sm.b.shoh[1][2] + (double)sm.b.s_ex[1][1];
        double sum1 = (double)sm.b.shoh[0][3] + (double)sm.b.shoh[1][3] + (double)sm.b.s_ex[1][0];
        if (cnt0 < 1.0) cnt0 = 1.0;
        if (cnt1 < 1.0) cnt1 = 1.0;
        double bce = (sm.b.shb[0] + sm.b.shb[1] + sm.b.shb[2] + sm.b.shb[3]) / (double)NPIX;
        out[0] = (float)(sum0 / cnt0 + sum1 / cnt1 + bce);
    }

    // ---- reset scratch for next call / graph replay ----
    __syncthreads();
    {
        float* oh = &g_oh[0][0][0];
        oh[tid] = 0.f;
        float* bb = &g_bce4[0][0][0];
        bb[tid] = 0.f; bb[tid + 256] = 0.f;
        int* ms = &g_ms[0][0][0];
        #pragma unroll
        for (int i = tid; i < 2 * NSLOT * 8; i += 256) ms[i] = 0;
        if (tid == 0) g_done = 0u;
    }
}

// ---------------- launch ----------------
extern "C" void kernel_launch(void* const* d_in, const int* in_sizes, int n_in,
                              void* d_out, int out_size)
{
    const float* mainp   = (const float*)d_in[0];
    const float* coarsep = (const float*)d_in[1];
    const float* bp      = (const float*)d_in[2];
    const int*   seg     = (const int*)d_in[3];
    const float* bgt     = (const float*)d_in[4];

    int nseg = in_sizes[3];
    int K = (nseg < 100000) ? nseg : 100000;

    fused_kernel<<<dim3(WO / 256, HO, B_), 256>>>(
        mainp, coarsep, seg, bp, bgt, (float*)d_out, K);
}

// round 15
// speedup vs baseline: 1.1127x; 1.1127x over previous
#include <cuda_runtime.h>
#include <cuda_fp16.h>

#define B_   4
#define C_   19
#define HI   64
#define WI   128
#define HO   512
#define WO   1024
#define NPIX   (B_*HO*WO)
#define NSLOT  64
#define SLOTSZ 32768
#define NCOL   40
#define LOG2E  1.4426950408889634f
#define LN2f   0.6931471805599453f
#define LP2T  (-0.5145731728f)   /* log2(0.7) */

typedef unsigned long long ull;

// ---------------- device scratch (zero at module load; tail kernel re-zeroes) ----
__device__ float    g_oh[2][2][64];        // [loss][{cnt,sum}][slot]
__device__ float    g_bce4[B_][4][32];     // [sample][{S1,S0,pos,neg}][slot]
__device__ int      g_ms[2][NSLOT][8];     // counter at [l][slot][0], 32B padded
__device__ uint2    g_comp[2][NPIX];       // 64 regions of 32768 per loss

__device__ __forceinline__ float ex2(float x) {
    float y; asm("ex2.approx.f32 %0, %1;" : "=f"(y) : "f"(x)); return y;
}
__device__ __forceinline__ float lg2(float x) {
    float y; asm("lg2.approx.f32 %0, %1;" : "=f"(y) : "f"(x)); return y;
}
__device__ __forceinline__ unsigned h2bits(float lo, float hi) {
    __half2 h = __floats2half2_rn(lo, hi);
    return *reinterpret_cast<unsigned*>(&h);
}
__device__ __forceinline__ ull packf2(float lo, float hi) {
    ull r; asm("mov.b64 %0, {%1, %2};" : "=l"(r) : "f"(lo), "f"(hi)); return r;
}
__device__ __forceinline__ ull addf2(ull a, ull b) {
    ull r; asm("add.rn.f32x2 %0, %1, %2;" : "=l"(r) : "l"(a), "l"(b)); return r;
}
__device__ __forceinline__ void unpackf2(ull v, float& lo, float& hi) {
    asm("mov.b64 {%0, %1}, %2;" : "=f"(lo), "=f"(hi) : "l"(v));
}

// ---------------- fused: upsample + softmax + OHEM accumulate + compaction + BCE ----
__global__ __launch_bounds__(256) void compute_kernel(
    const float* __restrict__ mainp,
    const float* __restrict__ coarsep,
    const int*   __restrict__ seg,
    const float* __restrict__ bp,
    const float* __restrict__ bgt)
{
    __shared__ uint2 prh[C_][NCOL];    // {half2(vm,vc), half2(dm,dc)} per (class,col)
    __shared__ float sred[8][8];

    const float SY = 63.f / 511.f;
    const float SX = 127.f / 1023.f;

    const int tid  = threadIdx.x;
    const int lane = tid & 31;
    const int warp = tid >> 5;
    const int oy = blockIdx.y;
    const int b  = blockIdx.z;
    const int xs = blockIdx.x * 256;
    const int blk  = blockIdx.x + 4 * (blockIdx.y + 512 * blockIdx.z);
    const int slot = blk & (NSLOT - 1);

    float fy  = oy * SY;
    int   y0  = (int)fy;
    int   y1  = min(y0 + 1, HI - 1);
    float wy  = fy - (float)y0;
    float w1y = 1.f - wy;

    int xbase4 = ((int)((float)xs * SX)) & ~3;   // 4-aligned; i0 in [0,35]

    const float* p0 = mainp   + (size_t)b * C_ * HI * WI;
    const float* p1 = coarsep + (size_t)b * C_ * HI * WI;

    // ---- stage 1: single pass, 171 tasks = (class, 4-col chunk), LDG.128 ----
    if (tid < C_ * 9) {
        int c = tid / 9;
        int k = tid - c * 9;
        int col0 = xbase4 + 4 * k;       // col0+3 <= 127 always
        int ce   = min(col0 + 4, WI - 1);

        const float* rm0 = p0 + c * HI * WI + y0 * WI;
        const float* rm1 = p0 + c * HI * WI + y1 * WI;
        const float* rc0 = p1 + c * HI * WI + y0 * WI;
        const float* rc1 = p1 + c * HI * WI + y1 * WI;

        float4 m0 = *(const float4*)(rm0 + col0);
        float4 m1 = *(const float4*)(rm1 + col0);
        float4 q0 = *(const float4*)(rc0 + col0);
        float4 q1 = *(const float4*)(rc1 + col0);
        float em0 = rm0[ce], em1 = rm1[ce];
        float ec0 = rc0[ce], ec1 = rc1[ce];

        float vm0 = (m0.x * w1y + m1.x * wy) * LOG2E;
        float vm1 = (m0.y * w1y + m1.y * wy) * LOG2E;
        float vm2 = (m0.z * w1y + m1.z * wy) * LOG2E;
        float vm3 = (m0.w * w1y + m1.w * wy) * LOG2E;
        float vm4 = (em0  * w1y + em1  * wy) * LOG2E;
        float vc0 = (q0.x * w1y + q1.x * wy) * LOG2E;
        float vc1 = (q0.y * w1y + q1.y * wy) * LOG2E;
        float vc2 = (q0.z * w1y + q1.z * wy) * LOG2E;
        float vc3 = (q0.w * w1y + q1.w * wy) * LOG2E;
        float vc4 = (ec0  * w1y + ec1  * wy) * LOG2E;

        prh[c][4*k + 0] = make_uint2(h2bits(vm0, vc0), h2bits(vm1 - vm0, vc1 - vc0));
        prh[c][4*k + 1] = make_uint2(h2bits(vm1, vc1), h2bits(vm2 - vm1, vc2 - vc1));
        prh[c][4*k + 2] = make_uint2(h2bits(vm2, vc2), h2bits(vm3 - vm2, vc3 - vc2));
        prh[c][4*k + 3] = make_uint2(h2bits(vm3, vc3), h2bits(vm4 - vm3, vc4 - vc3));
    }
    __syncthreads();

    int   ox = xs + tid;
    float fx = (float)ox * SX;
    int   x0 = (int)fx;
    float wx = fx - (float)x0;
    int   i0 = x0 - xbase4;              // [0, 35]

    int  pix   = (b * HO + oy) * WO + ox;
    int  t     = seg[pix];
    bool valid = (t != 255);
    int  tc    = valid ? t : 0;
    if (tc >= C_) tc = C_ - 1;

    const uint2* prq = &prh[0][0];
    __half2 wxh = __float2half2_rn(wx);

    // per class: LDS.64 + HFMA2 + h2exp2 (1 MUFU for both losses) + HADD2
    __half2 acc0 = __float2half2_rn(0.f);
    __half2 acc1 = __float2half2_rn(0.f);
    #pragma unroll
    for (int c = 0; c < C_; c++) {
        uint2 q = prq[c * NCOL + i0];
        __half2 v = *reinterpret_cast<__half2*>(&q.x);
        __half2 d = *reinterpret_cast<__half2*>(&q.y);
        __half2 e = h2exp2(__hfma2(wxh, d, v));
        if (c & 1) acc1 = __hadd2(acc1, e);
        else       acc0 = __hadd2(acc0, e);
    }
    __half2 acc = __hadd2(acc0, acc1);
    float s_main = __low2float(acc);
    float s_coar = __high2float(acc);

    float vtm, vtc;
    {
        uint2 q = prq[tc * NCOL + i0];
        __half2 v = *reinterpret_cast<__half2*>(&q.x);
        __half2 d = *reinterpret_cast<__half2*>(&q.y);
        __half2 vt2 = __hfma2(wxh, d, v);
        vtm = __low2float(vt2);
        vtc = __high2float(vt2);
    }

    float lp2m = vtm - lg2(s_main);
    float lp2c = vtc - lg2(s_coar);

    float c0f = 0.f, c1f = 0.f, r1 = 0.f, r3 = 0.f;
    #pragma unroll
    for (int l = 0; l < 2; l++) {
        float lp2 = l ? lp2c : lp2m;
        bool le = valid && (lp2 <= LP2T);           // prob <= 0.7 in log2 domain
        unsigned ble = __ballot_sync(0xffffffffu, le);
        if (l == 0) { c0f = (float)__popc(ble); if (le) r1 = -lp2 * LN2f; }
        else        { c1f = (float)__popc(ble); if (le) r3 = -lp2 * LN2f; }

        unsigned ball = ~ble;            // gt-set == complement (invalid -> prob=1)
        if (ball) {                      // warp-rare path: f32 EX2 only here
            int ldr = __ffs(ball) - 1;
            int base = 0;
            if (lane == ldr) base = atomicAdd(&g_ms[l][slot][0], __popc(ball));
            base = __shfl_sync(0xffffffffu, base, ldr);
            if (!le) {
                float prob = valid ? ex2(lp2) : 1.0f;
                float nll  = -lp2 * LN2f;
                int rank = __popc(ball & ((1u << lane) - 1u));
                g_comp[l][slot * SLOTSZ + base + rank] =
                    make_uint2(__float_as_uint(prob),
                               __float_as_uint(valid ? nll : -1e30f));
            }
        }
    }

    // ---- boundary BCE (fused) ----
    float tb = bgt[pix];
    const float* pb = bp + (size_t)b * HI * WI;
    int x1 = min(x0 + 1, WI - 1);
    float v00 = pb[y0 * WI + x0], v01 = pb[y0 * WI + x1];
    float v10 = pb[y1 * WI + x0], v11 = pb[y1 * WI + x1];
    float top = v00 * (1.f - wx) + v01 * wx;
    float bot = v10 * (1.f - wx) + v11 * wx;
    float p   = top * w1y + bot * wy;

    bool  isP = (tb == 1.0f), isN = (tb == 0.0f);
    float r4 = isP ? fminf(fmaxf(-lg2(p)       * LN2f, 0.f), 100.f) : 0.f;
    float r5 = isN ? fminf(fmaxf(-lg2(1.f - p) * LN2f, 0.f), 100.f) : 0.f;
    float cp = (float)__popc(__ballot_sync(~0u, isP));
    float cn = (float)__popc(__ballot_sync(~0u, isN));

    // ---- block reduce: packed f32x2 shfl chains (2 instead of 4) ----
    ull pA = packf2(r1, r3);
    ull pB = packf2(r4, r5);
    #pragma unroll
    for (int o = 16; o > 0; o >>= 1) {
        ull qA, qB;
        unsigned lo, hi;
        asm("mov.b64 {%0, %1}, %2;" : "=r"(lo), "=r"(hi) : "l"(pA));
        lo = __shfl_down_sync(~0u, lo, o); hi = __shfl_down_sync(~0u, hi, o);
        asm("mov.b64 %0, {%1, %2};" : "=l"(qA) : "r"(lo), "r"(hi));
        asm("mov.b64 {%0, %1}, %2;" : "=r"(lo), "=r"(hi) : "l"(pB));
        lo = __shfl_down_sync(~0u, lo, o); hi = __shfl_down_sync(~0u, hi, o);
        asm("mov.b64 %0, {%1, %2};" : "=l"(qB) : "r"(lo), "r"(hi));
        pA = addf2(pA, qA);
        pB = addf2(pB, qB);
    }
    unpackf2(pA, r1, r3);
    unpackf2(pB, r4, r5);
    if (lane == 0) {
        sred[warp][0] = c0f; sred[warp][1] = r1; sred[warp][2] = c1f; sred[warp][3] = r3;
        sred[warp][4] = r4;  sred[warp][5] = r5; sred[warp][6] = cp;  sred[warp][7] = cn;
    }
    __syncthreads();
    if (tid < 8) {
        float acc2 = 0.f;
        #pragma unroll
        for (int w = 0; w < 8; w++) acc2 += sred[w][tid];
        if (tid < 4) atomicAdd(&g_oh[tid >> 1][tid & 1][slot], acc2);
        else         atomicAdd(&g_bce4[b][tid - 4][blk & 31], acc2);
    }
}

// ---------------- tail: fallback select + finalize + scratch reset ----------------
__global__ __launch_bounds__(256) void tail_kernel(float* __restrict__ out, int K) {
    __shared__ unsigned hist[2048];
    __shared__ int      s_r;
    __shared__ unsigned s_pref;
    __shared__ float    s_cle[2];
    __shared__ float    redS[8], redC[8];
    __shared__ double   shb[4];
    __shared__ float    shoh[2][4];
    __shared__ float    s_ex[2][2];

    int tid = threadIdx.x, lane = tid & 31, w = tid >> 5;

    if (tid < 2) { s_ex[tid][0] = 0.f; s_ex[tid][1] = 0.f; }
    if (tid < 128) {
        float v = g_oh[tid >> 6][0][tid & 63];
        #pragma unroll
        for (int o = 16; o > 0; o >>= 1) v += __shfl_down_sync(~0u, v, o);
        if (lane == 0) redS[w] = v;
    }
    __syncthreads();
    if (tid < 2) s_cle[tid] = redS[tid * 2] + redS[tid * 2 + 1];
    __syncthreads();

    for (int l = 0; l < 2; l++) {
        int cLE = (int)(s_cle[l] + 0.5f);
        if (cLE >= K) continue;                 // common path: thr = 0.7 exactly

        if (tid == 0) { s_r = K - 1 - cLE; s_pref = 0u; }
        __syncthreads();

        for (int lev = 0; lev < 3; lev++) {
            for (int i = tid; i < 2048; i += 256) hist[i] = 0u;
            __syncthreads();
            unsigned pref = s_pref;
            for (int s = 0; s < NSLOT; s++) {
                int ms = g_ms[l][s][0];
                const uint2* sp = &g_comp[l][s * SLOTSZ];
                for (int i = tid; i < ms; i += 256) {
                    unsigned bits = sp[i].x;
                    bool ok; unsigned bin;
                    if (lev == 0)      { ok = true;                 bin = bits >> 21; }
                    else if (lev == 1) { ok = (bits >> 21) == pref; bin = (bits >> 10) & 0x7FFu; }
                    else               { ok = (bits >> 10) == pref; bin = bits & 0x3FFu; }
                    if (ok) atomicAdd(&hist[bin], 1u);
                }
            }
            __syncthreads();
            if (tid == 0) {
                int rr = s_r; unsigned cum = 0u;
                int nb = (lev == 2) ? 1024 : 2048;
                for (int i2 = 0; i2 < nb; i2++) {
                    unsigned h = hist[i2];
                    if ((int)(cum + h) > rr) {
                        s_pref = (lev == 0) ? (unsigned)i2
                               : (lev == 1) ? ((pref << 11) | (unsigned)i2)
                                            : ((pref << 10) | (unsigned)i2);
                        s_r = rr - (int)cum;
                        break;
                    }
                    cum += h;
                }
            }
            __syncthreads();
        }
        unsigned thr_bits = s_pref;

        float es = 0.f, ec = 0.f;
        for (int s = 0; s < NSLOT; s++) {
            int ms = g_ms[l][s][0];
            const uint2* sp = &g_comp[l][s * SLOTSZ];
            for (int i = tid; i < ms; i += 256) {
                uint2 e = sp[i];
                float nl = __uint_as_float(e.y);
                if (e.x <= thr_bits && nl > -1e29f) { es += nl; ec += 1.f; }
            }
        }
        #pragma unroll
        for (int o = 16; o > 0; o >>= 1) {
            es += __shfl_down_sync(~0u, es, o);
            ec += __shfl_down_sync(~0u, ec, o);
        }
        if (lane == 0) { redS[w] = es; redC[w] = ec; }
        __syncthreads();
        if (tid == 0) {
            float ts = 0.f, tc2 = 0.f;
            #pragma unroll
            for (int i = 0; i < 8; i++) { ts += redS[i]; tc2 += redC[i]; }
            s_ex[l][0] = ts; s_ex[l][1] = tc2;
        }
        __syncthreads();
    }

    // ---- finalize (first 128 threads) ----
    if (tid < 128) {
        float bs1  = g_bce4[w][0][lane];
        float bs0  = g_bce4[w][1][lane];
        float bpos = g_bce4[w][2][lane];
        float bneg = g_bce4[w][3][lane];
        float oc = 0.f, os = 0.f, oc1 = 0.f, os1 = 0.f;
        if (w < 2) {
            oc  = g_oh[0][0][tid]; os  = g_oh[0][1][tid];
            oc1 = g_oh[1][0][tid]; os1 = g_oh[1][1][tid];
        }
        #pragma unroll
        for (int o = 16; o > 0; o >>= 1) {
            bs1 += __shfl_down_sync(~0u, bs1, o); bs0 += __shfl_down_sync(~0u, bs0, o);
            bpos += __shfl_down_sync(~0u, bpos, o); bneg += __shfl_down_sync(~0u, bneg, o);
            oc += __shfl_down_sync(~0u, oc, o); os += __shfl_down_sync(~0u, os, o);
            oc1 += __shfl_down_sync(~0u, oc1, o); os1 += __shfl_down_sync(~0u, os1, o);
        }
        if (lane == 0) {
            double denom = (double)bpos + (double)bneg;
            shb[w] = ((double)bneg * (double)bs1 + (double)bpos * (double)bs0) / denom;
            if (w < 2) { shoh[w][0] = oc; shoh[w][1] = os; shoh[w][2] = oc1; shoh[w][3] = os1; }
        }
    }
    __syncthreads();
    if (tid == 0) {
        double cnt0 = (double)shoh[0][0] + (double)shoh[1][0] + (double)s_ex[0][1];
        double sum0 = (double)shoh[0][1] + (double)shoh[1][1] + (double)s_ex[0][0];
        double cnt1 = (double)shoh[0][2] + (double)shoh[1][2] + (double)s_ex[1][1];
        double sum1 = (double)shoh[0][3] + (double)shoh[1][3] + (double)s_ex[1][0];
        if (cnt0 < 1.0) cnt0 = 1.0;
        if (cnt1 < 1.0) cnt1 = 1.0;
        double bce = (shb[0] + shb[1] + shb[2] + shb[3]) / (double)NPIX;
        out[0] = (float)(sum0 / cnt0 + sum1 / cnt1 + bce);
    }

    // ---- reset scratch for next call / graph replay ----
    __syncthreads();
    {
        float* oh = &g_oh[0][0][0];
        oh[tid] = 0.f;
        float* bb = &g_bce4[0][0][0];
        bb[tid] = 0.f; bb[tid + 256] = 0.f;
        int* ms = &g_ms[0][0][0];
        #pragma unroll
        for (int i = tid; i < 2 * NSLOT * 8; i += 256) ms[i] = 0;
    }
}

// ---------------- launch ----------------
extern "C" void kernel_launch(void* const* d_in, const int* in_sizes, int n_in,
                              void* d_out, int out_size)
{
    const float* mainp   = (const float*)d_in[0];
    const float* coarsep = (const float*)d_in[1];
    const float* bp      = (const float*)d_in[2];
    const int*   seg     = (const int*)d_in[3];
    const float* bgt     = (const float*)d_in[4];

    int nseg = in_sizes[3];
    int K = (nseg < 100000) ? nseg : 100000;

    compute_kernel<<<dim3(WO / 256, HO, B_), 256>>>(mainp, coarsep, seg, bp, bgt);
    tail_kernel<<<1, 256>>>((float*)d_out, K);
}

// round 16
// speedup vs baseline: 1.1484x; 1.0321x over previous
#include <cuda_runtime.h>
#include <cuda_fp16.h>

#define B_   4
#define C_   19
#define HI   64
#define WI   128
#define HO   512
#define WO   1024
#define NPIX   (B_*HO*WO)
#define NSLOT  64
#define SLOTSZ 32768
#define NCOL   40
#define LOG2E  1.4426950408889634f
#define LN2f   0.6931471805599453f
#define LP2T  (-0.5145731728f)   /* log2(0.7) */

typedef unsigned long long ull;

// ---------------- device scratch (zero at module load; tail kernel re-zeroes) ----
__device__ float    g_oh[2][2][64];        // [loss][{cnt,sum}][slot]
__device__ float    g_bce4[B_][4][32];     // [sample][{S1,S0,pos,neg}][slot]
__device__ int      g_ms[2][NSLOT][8];     // counter at [l][slot][0], 32B padded
__device__ uint2    g_comp[2][NPIX];       // 64 regions of 32768 per loss

__device__ __forceinline__ float ex2(float x) {
    float y; asm("ex2.approx.f32 %0, %1;" : "=f"(y) : "f"(x)); return y;
}
__device__ __forceinline__ float lg2(float x) {
    float y; asm("lg2.approx.f32 %0, %1;" : "=f"(y) : "f"(x)); return y;
}
__device__ __forceinline__ unsigned h2bits(float lo, float hi) {
    __half2 h = __floats2half2_rn(lo, hi);
    return *reinterpret_cast<unsigned*>(&h);
}
__device__ __forceinline__ ull packf2(float lo, float hi) {
    ull r; asm("mov.b64 %0, {%1, %2};" : "=l"(r) : "f"(lo), "f"(hi)); return r;
}
__device__ __forceinline__ ull addf2(ull a, ull b) {
    ull r; asm("add.rn.f32x2 %0, %1, %2;" : "=l"(r) : "l"(a), "l"(b)); return r;
}
__device__ __forceinline__ void unpackf2(ull v, float& lo, float& hi) {
    asm("mov.b64 {%0, %1}, %2;" : "=f"(lo), "=f"(hi) : "l"(v));
}

// ---------------- fused: upsample + softmax + OHEM accumulate + compaction + BCE ----
__global__ __launch_bounds__(256, 7) void compute_kernel(
    const float* __restrict__ mainp,
    const float* __restrict__ coarsep,
    const int*   __restrict__ seg,
    const float* __restrict__ bp,
    const float* __restrict__ bgt)
{
    __shared__ uint2 prh[C_][NCOL];    // {half2(vm,vc), half2(dm,dc)} per (class,col)
    __shared__ float sred[8][8];

    const float SY = 63.f / 511.f;
    const float SX = 127.f / 1023.f;

    const int tid  = threadIdx.x;
    const int lane = tid & 31;
    const int warp = tid >> 5;
    const int oy = blockIdx.y;
    const int b  = blockIdx.z;
    const int xs = blockIdx.x * 256;
    const int blk  = blockIdx.x + 4 * (blockIdx.y + 512 * blockIdx.z);
    const int slot = blk & (NSLOT - 1);

    float fy  = oy * SY;
    int   y0  = (int)fy;
    int   y1  = min(y0 + 1, HI - 1);
    float wy  = fy - (float)y0;
    float w1y = 1.f - wy;

    int xbase4 = ((int)((float)xs * SX)) & ~3;   // 4-aligned; i0 in [0,35]

    const float* p0 = mainp   + (size_t)b * C_ * HI * WI;
    const float* p1 = coarsep + (size_t)b * C_ * HI * WI;

    // ---- stage 1: single pass, 171 tasks = (class, 4-col chunk), LDG.128 ----
    if (tid < C_ * 9) {
        int c = tid / 9;
        int k = tid - c * 9;
        int col0 = xbase4 + 4 * k;       // col0+3 <= 127 always
        int ce   = min(col0 + 4, WI - 1);

        const float* rm0 = p0 + c * HI * WI + y0 * WI;
        const float* rm1 = p0 + c * HI * WI + y1 * WI;
        const float* rc0 = p1 + c * HI * WI + y0 * WI;
        const float* rc1 = p1 + c * HI * WI + y1 * WI;

        float4 m0 = *(const float4*)(rm0 + col0);
        float4 m1 = *(const float4*)(rm1 + col0);
        float4 q0 = *(const float4*)(rc0 + col0);
        float4 q1 = *(const float4*)(rc1 + col0);
        float em0 = rm0[ce], em1 = rm1[ce];
        float ec0 = rc0[ce], ec1 = rc1[ce];

        float vm0 = (m0.x * w1y + m1.x * wy) * LOG2E;
        float vm1 = (m0.y * w1y + m1.y * wy) * LOG2E;
        float vm2 = (m0.z * w1y + m1.z * wy) * LOG2E;
        float vm3 = (m0.w * w1y + m1.w * wy) * LOG2E;
        float vm4 = (em0  * w1y + em1  * wy) * LOG2E;
        float vc0 = (q0.x * w1y + q1.x * wy) * LOG2E;
        float vc1 = (q0.y * w1y + q1.y * wy) * LOG2E;
        float vc2 = (q0.z * w1y + q1.z * wy) * LOG2E;
        float vc3 = (q0.w * w1y + q1.w * wy) * LOG2E;
        float vc4 = (ec0  * w1y + ec1  * wy) * LOG2E;

        prh[c][4*k + 0] = make_uint2(h2bits(vm0, vc0), h2bits(vm1 - vm0, vc1 - vc0));
        prh[c][4*k + 1] = make_uint2(h2bits(vm1, vc1), h2bits(vm2 - vm1, vc2 - vc1));
        prh[c][4*k + 2] = make_uint2(h2bits(vm2, vc2), h2bits(vm3 - vm2, vc3 - vc2));
        prh[c][4*k + 3] = make_uint2(h2bits(vm3, vc3), h2bits(vm4 - vm3, vc4 - vc3));
    }
    __syncthreads();

    int   ox = xs + tid;
    float fx = (float)ox * SX;
    int   x0 = (int)fx;
    float wx = fx - (float)x0;
    int   i0 = x0 - xbase4;              // [0, 35]

    int  pix   = (b * HO + oy) * WO + ox;
    int  t     = seg[pix];
    bool valid = (t != 255);
    int  tc    = valid ? t : 0;
    if (tc >= C_) tc = C_ - 1;

    const uint2* prq = &prh[0][0];
    __half2 wxh = __float2half2_rn(wx);

    // per class: LDS.64 + HFMA2 + h2exp2 (1 MUFU for both losses) + HADD2
    __half2 acc0 = __float2half2_rn(0.f);
    __half2 acc1 = __float2half2_rn(0.f);
    #pragma unroll
    for (int c = 0; c < C_; c++) {
        uint2 q = prq[c * NCOL + i0];
        __half2 v = *reinterpret_cast<__half2*>(&q.x);
        __half2 d = *reinterpret_cast<__half2*>(&q.y);
        __half2 e = h2exp2(__hfma2(wxh, d, v));
        if (c & 1) acc1 = __hadd2(acc1, e);
        else       acc0 = __hadd2(acc0, e);
    }
    __half2 acc = __hadd2(acc0, acc1);
    float s_main = __low2float(acc);
    float s_coar = __high2float(acc);

    float vtm, vtc;
    {
        uint2 q = prq[tc * NCOL + i0];
        __half2 v = *reinterpret_cast<__half2*>(&q.x);
        __half2 d = *reinterpret_cast<__half2*>(&q.y);
        __half2 vt2 = __hfma2(wxh, d, v);
        vtm = __low2float(vt2);
        vtc = __high2float(vt2);
    }

    float lp2m = vtm - lg2(s_main);
    float lp2c = vtc - lg2(s_coar);

    float c0f = 0.f, c1f = 0.f, r1 = 0.f, r3 = 0.f;
    #pragma unroll
    for (int l = 0; l < 2; l++) {
        float lp2 = l ? lp2c : lp2m;
        bool le = valid && (lp2 <= LP2T);           // prob <= 0.7 in log2 domain
        unsigned ble = __ballot_sync(0xffffffffu, le);
        if (l == 0) { c0f = (float)__popc(ble); if (le) r1 = -lp2 * LN2f; }
        else        { c1f = (float)__popc(ble); if (le) r3 = -lp2 * LN2f; }

        unsigned ball = ~ble;            // gt-set == complement (invalid -> prob=1)
        if (ball) {                      // warp-rare path: f32 EX2 only here
            int ldr = __ffs(ball) - 1;
            int base = 0;
            if (lane == ldr) base = atomicAdd(&g_ms[l][slot][0], __popc(ball));
            base = __shfl_sync(0xffffffffu, base, ldr);
            if (!le) {
                float prob = valid ? ex2(lp2) : 1.0f;
                float nll  = -lp2 * LN2f;
                int rank = __popc(ball & ((1u << lane) - 1u));
                g_comp[l][slot * SLOTSZ + base + rank] =
                    make_uint2(__float_as_uint(prob),
                               __float_as_uint(valid ? nll : -1e30f));
            }
        }
    }

    // ---- boundary BCE (fused) ----
    float tb = bgt[pix];
    const float* pb = bp + (size_t)b * HI * WI;
    int x1 = min(x0 + 1, WI - 1);
    float v00 = pb[y0 * WI + x0], v01 = pb[y0 * WI + x1];
    float v10 = pb[y1 * WI + x0], v11 = pb[y1 * WI + x1];
    float top = v00 * (1.f - wx) + v01 * wx;
    float bot = v10 * (1.f - wx) + v11 * wx;
    float p   = top * w1y + bot * wy;

    bool  isP = (tb == 1.0f), isN = (tb == 0.0f);
    float r4 = isP ? fminf(fmaxf(-lg2(p)       * LN2f, 0.f), 100.f) : 0.f;
    float r5 = isN ? fminf(fmaxf(-lg2(1.f - p) * LN2f, 0.f), 100.f) : 0.f;
    float cp = (float)__popc(__ballot_sync(~0u, isP));
    float cn = (float)__popc(__ballot_sync(~0u, isN));

    // ---- block reduce: packed f32x2 shfl chains (2 instead of 4) ----
    ull pA = packf2(r1, r3);
    ull pB = packf2(r4, r5);
    #pragma unroll
    for (int o = 16; o > 0; o >>= 1) {
        ull qA, qB;
        unsigned lo, hi;
        asm("mov.b64 {%0, %1}, %2;" : "=r"(lo), "=r"(hi) : "l"(pA));
        lo = __shfl_down_sync(~0u, lo, o); hi = __shfl_down_sync(~0u, hi, o);
        asm("mov.b64 %0, {%1, %2};" : "=l"(qA) : "r"(lo), "r"(hi));
        asm("mov.b64 {%0, %1}, %2;" : "=r"(lo), "=r"(hi) : "l"(pB));
        lo = __shfl_down_sync(~0u, lo, o); hi = __shfl_down_sync(~0u, hi, o);
        asm("mov.b64 %0, {%1, %2};" : "=l"(qB) : "r"(lo), "r"(hi));
        pA = addf2(pA, qA);
        pB = addf2(pB, qB);
    }
    unpackf2(pA, r1, r3);
    unpackf2(pB, r4, r5);
    if (lane == 0) {
        sred[warp][0] = c0f; sred[warp][1] = r1; sred[warp][2] = c1f; sred[warp][3] = r3;
        sred[warp][4] = r4;  sred[warp][5] = r5; sred[warp][6] = cp;  sred[warp][7] = cn;
    }
    __syncthreads();
    if (tid < 8) {
        float acc2 = 0.f;
        #pragma unroll
        for (int w = 0; w < 8; w++) acc2 += sred[w][tid];
        if (tid < 4) atomicAdd(&g_oh[tid >> 1][tid & 1][slot], acc2);
        else         atomicAdd(&g_bce4[b][tid - 4][blk & 31], acc2);
    }
}

// ---------------- tail: fallback select + finalize + scratch reset (PDL) ----------
__global__ __launch_bounds__(256) void tail_kernel(float* __restrict__ out, int K) {
    __shared__ unsigned hist[2048];
    __shared__ int      s_r;
    __shared__ unsigned s_pref;
    __shared__ float    s_cle[2];
    __shared__ float    redS[8], redC[8];
    __shared__ double   shb[4];
    __shared__ float    shoh[2][4];
    __shared__ float    s_ex[2][2];

    // PDL: wait for the primary (compute_kernel) to fully complete before
    // touching its results; our launch/prologue overlapped its tail wave.
    cudaGridDependencySynchronize();

    int tid = threadIdx.x, lane = tid & 31, w = tid >> 5;

    if (tid < 2) { s_ex[tid][0] = 0.f; s_ex[tid][1] = 0.f; }
    if (tid < 128) {
        float v = g_oh[tid >> 6][0][tid & 63];
        #pragma unroll
        for (int o = 16; o > 0; o >>= 1) v += __shfl_down_sync(~0u, v, o);
        if (lane == 0) redS[w] = v;
    }
    __syncthreads();
    if (tid < 2) s_cle[tid] = redS[tid * 2] + redS[tid * 2 + 1];
    __syncthreads();

    for (int l = 0; l < 2; l++) {
        int cLE = (int)(s_cle[l] + 0.5f);
        if (cLE >= K) continue;                 // common path: thr = 0.7 exactly

        if (tid == 0) { s_r = K - 1 - cLE; s_pref = 0u; }
        __syncthreads();

        for (int lev = 0; lev < 3; lev++) {
            for (int i = tid; i < 2048; i += 256) hist[i] = 0u;
            __syncthreads();
            unsigned pref = s_pref;
            for (int s = 0; s < NSLOT; s++) {
                int ms = g_ms[l][s][0];
                const uint2* sp = &g_comp[l][s * SLOTSZ];
                for (int i = tid; i < ms; i += 256) {
                    unsigned bits = sp[i].x;
                    bool ok; unsigned bin;
                    if (lev == 0)      { ok = true;                 bin = bits >> 21; }
                    else if (lev == 1) { ok = (bits >> 21) == pref; bin = (bits >> 10) & 0x7FFu; }
                    else               { ok = (bits >> 10) == pref; bin = bits & 0x3FFu; }
                    if (ok) atomicAdd(&hist[bin], 1u);
                }
            }
            __syncthreads();
            if (tid == 0) {
                int rr = s_r; unsigned cum = 0u;
                int nb = (lev == 2) ? 1024 : 2048;
                for (int i2 = 0; i2 < nb; i2++) {
                    unsigned h = hist[i2];
                    if ((int)(cum + h) > rr) {
                        s_pref = (lev == 0) ? (unsigned)i2
                               : (lev == 1) ? ((pref << 11) | (unsigned)i2)
                                            : ((pref << 10) | (unsigned)i2);
                        s_r = rr - (int)cum;
                        break;
                    }
                    cum += h;
                }
            }
            __syncthreads();
        }
        unsigned thr_bits = s_pref;

        float es = 0.f, ec = 0.f;
        for (int s = 0; s < NSLOT; s++) {
            int ms = g_ms[l][s][0];
            const uint2* sp = &g_comp[l][s * SLOTSZ];
            for (int i = tid; i < ms; i += 256) {
                uint2 e = sp[i];
                float nl = __uint_as_float(e.y);
                if (e.x <= thr_bits && nl > -1e29f) { es += nl; ec += 1.f; }
            }
        }
        #pragma unroll
        for (int o = 16; o > 0; o >>= 1) {
            es += __shfl_down_sync(~0u, es, o);
            ec += __shfl_down_sync(~0u, ec, o);
        }
        if (lane == 0) { redS[w] = es; redC[w] = ec; }
        __syncthreads();
        if (tid == 0) {
            float ts = 0.f, tc2 = 0.f;
            #pragma unroll
            for (int i = 0; i < 8; i++) { ts += redS[i]; tc2 += redC[i]; }
            s_ex[l][0] = ts; s_ex[l][1] = tc2;
        }
        __syncthreads();
    }

    // ---- finalize (first 128 threads) ----
    if (tid < 128) {
        float bs1  = g_bce4[w][0][lane];
        float bs0  = g_bce4[w][1][lane];
        float bpos = g_bce4[w][2][lane];
        float bneg = g_bce4[w][3][lane];
        float oc = 0.f, os = 0.f, oc1 = 0.f, os1 = 0.f;
        if (w < 2) {
            oc  = g_oh[0][0][tid]; os  = g_oh[0][1][tid];
            oc1 = g_oh[1][0][tid]; os1 = g_oh[1][1][tid];
        }
        #pragma unroll
        for (int o = 16; o > 0; o >>= 1) {
            bs1 += __shfl_down_sync(~0u, bs1, o); bs0 += __shfl_down_sync(~0u, bs0, o);
            bpos += __shfl_down_sync(~0u, bpos, o); bneg += __shfl_down_sync(~0u, bneg, o);
            oc += __shfl_down_sync(~0u, oc, o); os += __shfl_down_sync(~0u, os, o);
            oc1 += __shfl_down_sync(~0u, oc1, o); os1 += __shfl_down_sync(~0u, os1, o);
        }
        if (lane == 0) {
            double denom = (double)bpos + (double)bneg;
            shb[w] = ((double)bneg * (double)bs1 + (double)bpos * (double)bs0) / denom;
            if (w < 2) { shoh[w][0] = oc; shoh[w][1] = os; shoh[w][2] = oc1; shoh[w][3] = os1; }
        }
    }
    __syncthreads();
    if (tid == 0) {
        double cnt0 = (double)shoh[0][0] + (double)shoh[1][0] + (double)s_ex[0][1];
        double sum0 = (double)shoh[0][1] + (double)shoh[1][1] + (double)s_ex[0][0];
        double cnt1 = (double)shoh[0][2] + (double)shoh[1][2] + (double)s_ex[1][1];
        double sum1 = (double)shoh[0][3] + (double)shoh[1][3] + (double)s_ex[1][0];
        if (cnt0 < 1.0) cnt0 = 1.0;
        if (cnt1 < 1.0) cnt1 = 1.0;
        double bce = (shb[0] + shb[1] + shb[2] + shb[3]) / (double)NPIX;
        out[0] = (float)(sum0 / cnt0 + sum1 / cnt1 + bce);
    }

    // ---- reset scratch for next call / graph replay ----
    __syncthreads();
    {
        float* oh = &g_oh[0][0][0];
        oh[tid] = 0.f;
        float* bb = &g_bce4[0][0][0];
        bb[tid] = 0.f; bb[tid + 256] = 0.f;
        int* ms = &g_ms[0][0][0];
        #pragma unroll
        for (int i = tid; i < 2 * NSLOT * 8; i += 256) ms[i] = 0;
    }
}

// ---------------- launch ----------------
extern "C" void kernel_launch(void* const* d_in, const int* in_sizes, int n_in,
                              void* d_out, int out_size)
{
    const float* mainp   = (const float*)d_in[0];
    const float* coarsep = (const float*)d_in[1];
    const float* bp      = (const float*)d_in[2];
    const int*   seg     = (const int*)d_in[3];
    const float* bgt     = (const float*)d_in[4];

    int nseg = in_sizes[3];
    int K = (nseg < 100000) ? nseg : 100000;

    compute_kernel<<<dim3(WO / 256, HO, B_), 256>>>(mainp, coarsep, seg, bp, bgt);

    // Tail launched with Programmatic Dependent Launch: its launch/prologue
    // overlaps the compute kernel's final wave; it synchronizes via
    // cudaGridDependencySynchronize() before reading results.
    cudaLaunchConfig_t cfg = {};
    cfg.gridDim  = dim3(1, 1, 1);
    cfg.blockDim = dim3(256, 1, 1);
    cfg.dynamicSmemBytes = 0;
    cfg.stream = 0;
    cudaLaunchAttribute attrs[1];
    attrs[0].id = cudaLaunchAttributeProgrammaticStreamSerialization;
    attrs[0].val.programmaticStreamSerializationAllowed = 1;
    cfg.attrs = attrs;
    cfg.numAttrs = 1;
    cudaLaunchKernelEx(&cfg, tail_kernel, (float*)d_out, K);
}